// round 1
// baseline (speedup 1.0000x reference)
#include <cuda_runtime.h>
#include <cuda_bf16.h>
#include <math.h>

// Problem constants
#define NX   2048
#define NY   2048
#define DIM  28
#define PACK_W 12   // 10 used words + 2 pad, 16B aligned for uint4 loads

// Packed signatures: per sample, words [0..6] = value one-hot (8 bits/pos),
// words [7..9] = class one-hot (3 bits/pos, 10 positions per word), [10..11]=0.
__device__ unsigned int g_pr[NX * PACK_W];
__device__ unsigned int g_pt[NY * PACK_W];

// class(v) for v in [0,8): {1,1,1,0,0,0,0,2} -> 2-bit packed constant
#define CLS_PACK 0x8015u  // (1)|(1<<2)|(1<<4)|(2<<14)

__global__ void pack_kernel(const int* __restrict__ set, unsigned int* __restrict__ out, int n)
{
    int i = blockIdx.x * blockDim.x + threadIdx.x;
    if (i >= n) return;
    const int* s = set + i * DIM;
    unsigned int w[PACK_W];
#pragma unroll
    for (int k = 0; k < PACK_W; k++) w[k] = 0u;
#pragma unroll
    for (int p = 0; p < DIM; p++) {
        int v = s[p];
        w[p >> 2] |= 1u << (((p & 3) << 3) + v);
        unsigned int c = (CLS_PACK >> (2 * v)) & 3u;
        w[7 + p / 10] |= 1u << ((p % 10) * 3 + c);
    }
    uint4* o = (uint4*)(out + i * PACK_W);
    o[0] = make_uint4(w[0], w[1], w[2],  w[3]);
    o[1] = make_uint4(w[4], w[5], w[6],  w[7]);
    o[2] = make_uint4(w[8], w[9], w[10], w[11]);
}

// Tile: 64x64 outputs per block, 256 threads (16x16), 4x4 outputs per thread.
#define TS 64
__global__ __launch_bounds__(256) void dist_kernel(const float* __restrict__ sigma_ptr,
                                                   float* __restrict__ out)
{
    __shared__ unsigned int rsh[TS * PACK_W];
    __shared__ unsigned int tsh[TS * PACK_W];
    __shared__ float lut[57];

    const int tid = threadIdx.x;
    const int i0 = blockIdx.y * TS;
    const int j0 = blockIdx.x * TS;

    // cooperative tile load (uint4): TS*PACK_W/4 = 192 uint4 per tile
    {
        const uint4* rg = (const uint4*)(g_pr + i0 * PACK_W);
        const uint4* tg = (const uint4*)(g_pt + j0 * PACK_W);
        uint4* rs = (uint4*)rsh;
        uint4* ts = (uint4*)tsh;
#pragma unroll
        for (int k = tid; k < TS * PACK_W / 4; k += 256) {
            rs[k] = rg[k];
            ts[k] = tg[k];
        }
    }
    if (tid < 57) {
        float sig = *sigma_ptr;
        float d = (float)(56 - tid) * (1.0f / 28.0f);
        lut[tid] = expf(-d * d / (2.0f * sig * sig));
    }
    __syncthreads();

    const int tx = tid & 15;        // j sub-tile
    const int ty = tid >> 4;        // i sub-tile
    const int jb = tx << 2;
    const int ib = ty << 2;

    // hold 4 t-signatures in registers
    unsigned int t0[10], t1[10], t2[10], t3[10];
#pragma unroll
    for (int w = 0; w < 10; w++) {
        t0[w] = tsh[(jb + 0) * PACK_W + w];
        t1[w] = tsh[(jb + 1) * PACK_W + w];
        t2[w] = tsh[(jb + 2) * PACK_W + w];
        t3[w] = tsh[(jb + 3) * PACK_W + w];
    }

#pragma unroll
    for (int r = 0; r < 4; r++) {
        unsigned int a[10];
#pragma unroll
        for (int w = 0; w < 10; w++) a[w] = rsh[(ib + r) * PACK_W + w];

        int s0 = 0, s1 = 0, s2 = 0, s3 = 0;
#pragma unroll
        for (int w = 0; w < 10; w++) {
            s0 += __popc(a[w] & t0[w]);
            s1 += __popc(a[w] & t1[w]);
            s2 += __popc(a[w] & t2[w]);
            s3 += __popc(a[w] & t3[w]);
        }
        float4 o;
        o.x = lut[s0]; o.y = lut[s1]; o.z = lut[s2]; o.w = lut[s3];
        *(float4*)(out + (size_t)(i0 + ib + r) * NY + j0 + jb) = o;
    }
}

extern "C" void kernel_launch(void* const* d_in, const int* in_sizes, int n_in,
                              void* d_out, int out_size)
{
    const int*   set_r = (const int*)d_in[0];
    const int*   set_t = (const int*)d_in[1];
    const float* sigma = (const float*)d_in[2];
    float*       out   = (float*)d_out;

    unsigned int* pr = nullptr;
    unsigned int* pt = nullptr;
    cudaGetSymbolAddress((void**)&pr, g_pr);
    cudaGetSymbolAddress((void**)&pt, g_pt);

    pack_kernel<<<(NX + 255) / 256, 256>>>(set_r, pr, NX);
    pack_kernel<<<(NY + 255) / 256, 256>>>(set_t, pt, NY);

    dim3 grid(NY / TS, NX / TS);
    dist_kernel<<<grid, 256>>>(sigma, out);
}

// round 3
// speedup vs baseline: 1.1791x; 1.1791x over previous
#include <cuda_runtime.h>
#include <cuda_bf16.h>
#include <math.h>

// Problem constants
#define NX   2048
#define NY   2048
#define DIM  28
#define PACK_W 12   // 10 used words + 2 zero pad -> 48B row, 16B aligned

// class(v) for v in [0,8): {1,1,1,0,0,0,0,2} packed 2 bits per value
#define CLS_PACK 0x8015u

#define TS 64

// Fused kernel: each block packs the 64 r-rows and 64 t-rows it needs into
// shared memory, then computes the 64x64 output tile with bit-signature
// AND+popcount and a 57-entry exp LUT.
//
// Signature layout per row (10 words):
//   w[0..6]: value one-hot, 8 bits per position (4 positions per word)
//   w[7..9]: class one-hot, 3 bits per position (10 positions per word)
// popc(sig_r & sig_t) = eq_cnt + cls_cnt = 56 - 28*dist
__global__ __launch_bounds__(256) void fused_kernel(const int* __restrict__ set_r,
                                                    const int* __restrict__ set_t,
                                                    const float* __restrict__ sigma_ptr,
                                                    float* __restrict__ out)
{
    __shared__ unsigned int rsh[TS * PACK_W];
    __shared__ unsigned int tsh[TS * PACK_W];
    __shared__ float lut[57];

    const int tid = threadIdx.x;
    const int i0 = blockIdx.y * TS;
    const int j0 = blockIdx.x * TS;

    // ---- pack phase: threads 0..63 pack r rows, 64..127 pack t rows ----
    if (tid < 128) {
        const int row = tid & 63;
        const int* src = (tid < 64) ? (set_r + (size_t)(i0 + row) * DIM)
                                    : (set_t + (size_t)(j0 + row) * DIM);
        unsigned int* dst = ((tid < 64) ? rsh : tsh) + row * PACK_W;

        // 28 ints as 7 x uint4 loads
        uint4 raw[7];
        const uint4* s4 = (const uint4*)src;
#pragma unroll
        for (int k = 0; k < 7; k++) raw[k] = s4[k];
        const int* v = (const int*)raw;

        unsigned int w[PACK_W];
#pragma unroll
        for (int k = 0; k < PACK_W; k++) w[k] = 0u;
#pragma unroll
        for (int p = 0; p < DIM; p++) {
            int vv = v[p];
            w[p >> 2] |= 1u << (((p & 3) << 3) + vv);
            unsigned int c = (CLS_PACK >> (2 * vv)) & 3u;
            w[7 + p / 10] |= 1u << ((p % 10) * 3 + c);
        }
        uint4* d4 = (uint4*)dst;
        d4[0] = make_uint4(w[0], w[1], w[2],  w[3]);
        d4[1] = make_uint4(w[4], w[5], w[6],  w[7]);
        d4[2] = make_uint4(w[8], w[9], 0u, 0u);
    } else if (tid - 128 < 57) {
        const int s = tid - 128;
        float sig = *sigma_ptr;
        float d = (float)(56 - s) * (1.0f / 28.0f);
        lut[s] = expf(-d * d / (2.0f * sig * sig));
    }
    __syncthreads();

    // ---- compute phase: 16x16 threads, 4x4 outputs each ----
    const int tx = tid & 15;
    const int ty = tid >> 4;
    const int jb = tx << 2;
    const int ib = ty << 2;

    unsigned int t0[10], t1[10], t2[10], t3[10];
    {
        const uint4* b0 = (const uint4*)(tsh + (jb + 0) * PACK_W);
        const uint4* b1 = (const uint4*)(tsh + (jb + 1) * PACK_W);
        const uint4* b2 = (const uint4*)(tsh + (jb + 2) * PACK_W);
        const uint4* b3 = (const uint4*)(tsh + (jb + 3) * PACK_W);
        uint4 q;
        q = b0[0]; t0[0]=q.x; t0[1]=q.y; t0[2]=q.z; t0[3]=q.w;
        q = b0[1]; t0[4]=q.x; t0[5]=q.y; t0[6]=q.z; t0[7]=q.w;
        q = b0[2]; t0[8]=q.x; t0[9]=q.y;
        q = b1[0]; t1[0]=q.x; t1[1]=q.y; t1[2]=q.z; t1[3]=q.w;
        q = b1[1]; t1[4]=q.x; t1[5]=q.y; t1[6]=q.z; t1[7]=q.w;
        q = b1[2]; t1[8]=q.x; t1[9]=q.y;
        q = b2[0]; t2[0]=q.x; t2[1]=q.y; t2[2]=q.z; t2[3]=q.w;
        q = b2[1]; t2[4]=q.x; t2[5]=q.y; t2[6]=q.z; t2[7]=q.w;
        q = b2[2]; t2[8]=q.x; t2[9]=q.y;
        q = b3[0]; t3[0]=q.x; t3[1]=q.y; t3[2]=q.z; t3[3]=q.w;
        q = b3[1]; t3[4]=q.x; t3[5]=q.y; t3[6]=q.z; t3[7]=q.w;
        q = b3[2]; t3[8]=q.x; t3[9]=q.y;
    }

#pragma unroll
    for (int r = 0; r < 4; r++) {
        unsigned int a[10];
        const uint4* ar = (const uint4*)(rsh + (ib + r) * PACK_W);
        uint4 q;
        q = ar[0]; a[0]=q.x; a[1]=q.y; a[2]=q.z; a[3]=q.w;
        q = ar[1]; a[4]=q.x; a[5]=q.y; a[6]=q.z; a[7]=q.w;
        q = ar[2]; a[8]=q.x; a[9]=q.y;

        int s0 = 0, s1 = 0, s2 = 0, s3 = 0;
#pragma unroll
        for (int w = 0; w < 10; w++) {
            s0 += __popc(a[w] & t0[w]);
            s1 += __popc(a[w] & t1[w]);
            s2 += __popc(a[w] & t2[w]);
            s3 += __popc(a[w] & t3[w]);
        }
        float4 o;
        o.x = lut[s0]; o.y = lut[s1]; o.z = lut[s2]; o.w = lut[s3];
        *(float4*)(out + (size_t)(i0 + ib + r) * NY + j0 + jb) = o;
    }
}

extern "C" void kernel_launch(void* const* d_in, const int* in_sizes, int n_in,
                              void* d_out, int out_size)
{
    const int*   set_r = (const int*)d_in[0];
    const int*   set_t = (const int*)d_in[1];
    const float* sigma = (const float*)d_in[2];
    float*       out   = (float*)d_out;

    dim3 grid(NY / TS, NX / TS);
    fused_kernel<<<grid, 256>>>(set_r, set_t, sigma, out);
}

// round 5
// speedup vs baseline: 1.8922x; 1.6048x over previous
#include <cuda_runtime.h>
#include <cuda_bf16.h>
#include <math.h>

// Problem constants
#define NX   2048
#define NY   2048
#define DIM  28
#define TS   64   // 64x64 output tile per block, 256 threads, 4x4 per thread

// Bitplane signatures, 5 words per row:
//   plane 0..2 : value bits 0..2   (28 positions -> bits [0,28))
//   plane 3    : class bit 0  (v <= 2)
//   plane 4    : class bit 1  (v == 7)
// Per pair:  vd = OR of value-plane XORs  -> bit set iff values differ
//            cd = OR of class-plane XORs  -> bit set iff classes differ
//            dist_sum = popc(vd) + popc(cd)   (0 / 1 / 2 per position)
__global__ __launch_bounds__(256) void fused_kernel(const int* __restrict__ set_r,
                                                    const int* __restrict__ set_t,
                                                    const float* __restrict__ sigma_ptr,
                                                    float* __restrict__ out)
{
    __shared__ unsigned int rsh[5 * TS];   // plane-major: [plane*64 + row]
    __shared__ unsigned int tsh[5 * TS];
    __shared__ float lut[57];

    const int tid = threadIdx.x;
    const int i0 = blockIdx.y * TS;
    const int j0 = blockIdx.x * TS;

    // ---- pack phase ----
    if (tid < 128) {
        const int row = tid & 63;
        const bool is_r = (tid < 64);
        const int* src = is_r ? (set_r + (size_t)(i0 + row) * DIM)
                              : (set_t + (size_t)(j0 + row) * DIM);
        unsigned int* sh = is_r ? rsh : tsh;

        uint4 raw[7];
        const uint4* s4 = (const uint4*)src;
#pragma unroll
        for (int k = 0; k < 7; k++) raw[k] = s4[k];
        const int* v = (const int*)raw;

        unsigned int b0 = 0, b1 = 0, b2 = 0, c0 = 0, c1 = 0;
#pragma unroll
        for (int p = 0; p < DIM; p++) {
            unsigned int vv = (unsigned int)v[p];
            b0 |= (vv & 1u) << p;
            b1 |= ((vv >> 1) & 1u) << p;
            b2 |= ((vv >> 2) & 1u) << p;
            c0 |= (unsigned int)(vv <= 2u) << p;
            c1 |= (unsigned int)(vv == 7u) << p;
        }
        sh[0 * TS + row] = b0;
        sh[1 * TS + row] = b1;
        sh[2 * TS + row] = b2;
        sh[3 * TS + row] = c0;
        sh[4 * TS + row] = c1;
    } else if (tid - 128 < 57) {
        const int s = tid - 128;
        float sig = *sigma_ptr;
        float d = (float)s * (1.0f / 28.0f);
        lut[s] = expf(-d * d / (2.0f * sig * sig));
    }
    __syncthreads();

    // ---- compute phase: 16x16 threads, 4x4 outputs per thread ----
    const int tx = tid & 15;
    const int ty = tid >> 4;
    const int jb = tx << 2;
    const int ib = ty << 2;

    // 4 t-signatures in registers (20 words)
    unsigned int tt[4][5];
#pragma unroll
    for (int p = 0; p < 5; p++) {
#pragma unroll
        for (int k = 0; k < 4; k++)
            tt[k][p] = tsh[p * TS + jb + k];
    }

#pragma unroll
    for (int r = 0; r < 4; r++) {
        const int arow = ib + r;
        const unsigned int a0 = rsh[0 * TS + arow];   // broadcast within half-warp
        const unsigned int a1 = rsh[1 * TS + arow];
        const unsigned int a2 = rsh[2 * TS + arow];
        const unsigned int a3 = rsh[3 * TS + arow];
        const unsigned int a4 = rsh[4 * TS + arow];

        float o[4];
#pragma unroll
        for (int k = 0; k < 4; k++) {
            unsigned int vd = (a0 ^ tt[k][0]) | (a1 ^ tt[k][1]) | (a2 ^ tt[k][2]);
            unsigned int cd = (a3 ^ tt[k][3]) | (a4 ^ tt[k][4]);
            int s = __popc(vd) + __popc(cd);
            o[k] = lut[s];
        }
        float4 q = make_float4(o[0], o[1], o[2], o[3]);
        *(float4*)(out + (size_t)(i0 + arow) * NY + j0 + jb) = q;
    }
}

extern "C" void kernel_launch(void* const* d_in, const int* in_sizes, int n_in,
                              void* d_out, int out_size)
{
    const int*   set_r = (const int*)d_in[0];
    const int*   set_t = (const int*)d_in[1];
    const float* sigma = (const float*)d_in[2];
    float*       out   = (float*)d_out;

    dim3 grid(NY / TS, NX / TS);
    fused_kernel<<<grid, 256>>>(set_r, set_t, sigma, out);
}

// round 6
// speedup vs baseline: 1.9506x; 1.0309x over previous
#include <cuda_runtime.h>
#include <cuda_bf16.h>
#include <math.h>

// Problem constants
#define NX   2048
#define NY   2048
#define DIM  28
#define TS   128   // 128x128 output tile per block, 256 threads, 8x8 per thread

// Bitplane signatures, 5 words per row:
//   plane 0..2 : value bits 0..2   (28 positions -> bits [0,28))
//   plane 3    : class bit 0  (v <= 2)
//   plane 4    : class bit 1  (v == 7)
// Per pair:  vd = OR of value-plane XORs (bit set iff values differ)
//            cd = OR of class-plane XORs (bit set iff classes differ; cd ⊆ vd)
//            dist_sum = popc(vd) + popc(cd)  in [0,56]
__global__ __launch_bounds__(256, 4) void fused_kernel(const int* __restrict__ set_r,
                                                       const int* __restrict__ set_t,
                                                       const float* __restrict__ sigma_ptr,
                                                       float* __restrict__ out)
{
    __shared__ unsigned int rsh[5][TS];   // plane-major
    __shared__ unsigned int tsh[5][TS];
    __shared__ float lut[57];

    const int tid = threadIdx.x;
    const int i0 = blockIdx.y * TS;
    const int j0 = blockIdx.x * TS;

    // ---- pack phase: 256 threads, one row each (128 r + 128 t) ----
    {
        const int row = tid & 127;
        const bool is_r = (tid < 128);
        const int* src = is_r ? (set_r + (size_t)(i0 + row) * DIM)
                              : (set_t + (size_t)(j0 + row) * DIM);

        uint4 raw[7];
        const uint4* s4 = (const uint4*)src;
#pragma unroll
        for (int k = 0; k < 7; k++) raw[k] = s4[k];
        const int* v = (const int*)raw;

        unsigned int b0 = 0, b1 = 0, b2 = 0, c0 = 0, c1 = 0;
#pragma unroll
        for (int p = 0; p < DIM; p++) {
            unsigned int vv = (unsigned int)v[p];
            b0 |= (vv & 1u) << p;
            b1 |= ((vv >> 1) & 1u) << p;
            b2 |= ((vv >> 2) & 1u) << p;
            c0 |= (unsigned int)(vv <= 2u) << p;
            c1 |= (unsigned int)(vv == 7u) << p;
        }
        if (is_r) {
            rsh[0][row] = b0; rsh[1][row] = b1; rsh[2][row] = b2;
            rsh[3][row] = c0; rsh[4][row] = c1;
        } else {
            tsh[0][row] = b0; tsh[1][row] = b1; tsh[2][row] = b2;
            tsh[3][row] = c0; tsh[4][row] = c1;
        }
    }
    if (tid < 57) {
        float sig = *sigma_ptr;
        float d = (float)tid * (1.0f / 28.0f);
        lut[tid] = expf(-d * d / (2.0f * sig * sig));
    }
    __syncthreads();

    // ---- compute phase: 16x16 threads; each owns cols {4tx, 4tx+64}+0..3
    //      and rows {4ty, 4ty+64}+0..3  -> 8x8 outputs ----
    const int tx = tid & 15;
    const int ty = tid >> 4;

#pragma unroll
    for (int kj = 0; kj < 2; kj++) {
        const int jb = 4 * tx + 64 * kj;
        // 4 t-columns, 5 planes as uint4 (component c = column jb+c)
        uint4 tq[5];
#pragma unroll
        for (int p = 0; p < 5; p++) tq[p] = *(const uint4*)&tsh[p][jb];

#pragma unroll
        for (int ki = 0; ki < 2; ki++) {
            const int ib = 4 * ty + 64 * ki;
            // 4 a-rows, 5 planes as uint4 (component r = row ib+r)
            uint4 aq[5];
#pragma unroll
            for (int p = 0; p < 5; p++) aq[p] = *(const uint4*)&rsh[p][ib];

#pragma unroll
            for (int r = 0; r < 4; r++) {
                const unsigned int a0 = ((const unsigned int*)&aq[0])[r];
                const unsigned int a1 = ((const unsigned int*)&aq[1])[r];
                const unsigned int a2 = ((const unsigned int*)&aq[2])[r];
                const unsigned int a3 = ((const unsigned int*)&aq[3])[r];
                const unsigned int a4 = ((const unsigned int*)&aq[4])[r];

                float o[4];
#pragma unroll
                for (int c = 0; c < 4; c++) {
                    unsigned int vd = (a0 ^ ((const unsigned int*)&tq[0])[c])
                                    | (a1 ^ ((const unsigned int*)&tq[1])[c])
                                    | (a2 ^ ((const unsigned int*)&tq[2])[c]);
                    unsigned int cd = (a3 ^ ((const unsigned int*)&tq[3])[c])
                                    | (a4 ^ ((const unsigned int*)&tq[4])[c]);
                    int s = __popc(vd) + __popc(cd);
                    o[c] = lut[s];
                }
                float4 q = make_float4(o[0], o[1], o[2], o[3]);
                *(float4*)(out + (size_t)(i0 + ib + r) * NY + j0 + jb) = q;
            }
        }
    }
}

extern "C" void kernel_launch(void* const* d_in, const int* in_sizes, int n_in,
                              void* d_out, int out_size)
{
    const int*   set_r = (const int*)d_in[0];
    const int*   set_t = (const int*)d_in[1];
    const float* sigma = (const float*)d_in[2];
    float*       out   = (float*)d_out;

    dim3 grid(NY / TS, NX / TS);
    fused_kernel<<<grid, 256>>>(set_r, set_t, sigma, out);
}